// round 8
// baseline (speedup 1.0000x reference)
#include <cuda_runtime.h>
#include <cuda_fp16.h>
#include <cstdint>

#define Bq    8
#define CIN   128
#define COUT  128
#define HH    256
#define WW    256
#define SDIM  512

#define PXW   20     // words (half2) per px row in stage; 20 = 4*5 -> conflict-free
#define NPX   258    // full row + halo

__device__ float  g_style[Bq * CIN];
__device__ float  g_demod[Bq * COUT];
__device__ float  g_W2[COUT * CIN];
__device__ __half g_wA[36 * 8192];   // fragment-ordered fp16 weights (proven R6/R7 mapping)

#define MMA_F16(d, a, bb)                                                 \
    asm volatile("mma.sync.aligned.m16n8k16.row.col.f32.f16.f16.f32 "     \
                 "{%0,%1,%2,%3}, {%4,%5,%6,%7}, {%8,%9}, {%0,%1,%2,%3};"  \
                 : "+f"((d)[0]), "+f"((d)[1]), "+f"((d)[2]), "+f"((d)[3]) \
                 : "r"((a)[0]), "r"((a)[1]), "r"((a)[2]), "r"((a)[3]),    \
                   "r"((bb)[0]), "r"((bb)[1]))

// ---------------------------------------------------------------------------
// prep1: blocks 0..127 = style GEMV (warp per (b,o)); blocks 128..191 = W2
// ---------------------------------------------------------------------------
__global__ void prep1(const float* __restrict__ w,
                      const float* __restrict__ style_W,
                      const float* __restrict__ style_b,
                      const float* __restrict__ weight) {
    if (blockIdx.x < 128) {
        const int gw   = blockIdx.x * 8 + (threadIdx.x >> 5);  // 0..1023
        const int lane = threadIdx.x & 31;
        const int b = gw >> 7, o = gw & 127;
        const float4* wv = (const float4*)(w + (size_t)b * SDIM);
        const float4* Wv = (const float4*)(style_W + (size_t)o * SDIM);
        float acc = 0.f;
        #pragma unroll
        for (int k = 0; k < 4; k++) {
            float4 a = wv[lane + k * 32], c = Wv[lane + k * 32];
            acc += a.x * c.x + a.y * c.y + a.z * c.z + a.w * c.w;
        }
        #pragma unroll
        for (int d = 16; d > 0; d >>= 1)
            acc += __shfl_xor_sync(0xffffffffu, acc, d);
        if (lane == 0) g_style[b * CIN + o] = acc + style_b[o];
    } else {
        int idx = (blockIdx.x - 128) * 256 + threadIdx.x;   // < 16384
        const float* p = weight + (size_t)idx * 9;
        float s = 0.f;
        #pragma unroll
        for (int t = 0; t < 9; t++) { float v = p[t]; s += v * v; }
        g_W2[idx] = s;
    }
}

// ---------------------------------------------------------------------------
// prep2: prepack (blocks 0..1151) + demod (blocks 1152..1279)
// ---------------------------------------------------------------------------
__global__ void prep2(const float* __restrict__ weight) {
    if (blockIdx.x < 1152) {
        int idx = blockIdx.x * 256 + threadIdx.x;      // < 294912
        int h    = idx & 1;
        int j    = (idx >> 1) & 3;
        int lane = (idx >> 3) & 31;
        int mt   = (idx >> 8) & 7;
        int kk   = (idx >> 11) & 1;
        int s    = idx >> 12;                          // 0..35
        int dx = s % 3;
        int g  = s / 3;
        int dy = g >> 2, chunk = g & 3;
        int m  = mt * 16 + (lane >> 2) + 8 * (j & 1);
        int kl = kk * 16 + (lane & 3) * 2 + 8 * (j >> 1) + h;
        int c  = chunk * 32 + kl;
        g_wA[idx] = __float2half_rn(weight[((size_t)m * CIN + c) * 9 + dy * 3 + dx]);
    } else {
        int gw   = (blockIdx.x - 1152) * 8 + (threadIdx.x >> 5);
        int lane = threadIdx.x & 31;
        int b = gw >> 7, o = gw & 127;
        float sum = 0.f;
        #pragma unroll
        for (int j = 0; j < 4; j++) {
            int i = lane + j * 32;
            float s = g_style[b * CIN + i];
            sum += s * s * g_W2[o * CIN + i];
        }
        #pragma unroll
        for (int d = 16; d > 0; d >>= 1)
            sum += __shfl_xor_sync(0xffffffffu, sum, d);
        if (lane == 0) g_demod[b * COUT + o] = rsqrtf(sum + 1e-8f);
    }
}

// ---------------------------------------------------------------------------
// main conv: CTA = (y, b). M=128 x N=256 x K=1152, fp16 m16n8k16.
// 16 warps = 2(wm) x 8(wn); warp tile 64x32; register-prefetched fill.
// ---------------------------------------------------------------------------
__global__ __launch_bounds__(512, 1)
void conv_mma_kernel(const float* __restrict__ x,
                     const float* __restrict__ bias,
                     float* __restrict__ out) {
    __shared__ float    styl[CIN];
    __shared__ uint32_t stage[2][NPX * PXW];

    const int tid  = threadIdx.x;
    const int lane = tid & 31;
    const int warp = tid >> 5;
    const int wm   = warp >> 3;      // 0..1
    const int wn   = warp & 7;       // 0..7
    const int y    = blockIdx.x;
    const int b    = blockIdx.y;

    const int gid = lane >> 2;       // 0..7
    const int tig = lane & 3;        // 0..3

    if (tid < CIN) styl[tid] = g_style[b * CIN + tid];
    __syncthreads();

    float acc[4][4][4];
    #pragma unroll
    for (int m = 0; m < 4; m++)
        #pragma unroll
        for (int n = 0; n < 4; n++)
            #pragma unroll
            for (int j = 0; j < 4; j++) acc[m][n][j] = 0.f;

    // fill mapping: jj(2) x ii(4): px = jj*128 + (tid>>2), cp = (tid&3) + 4*ii
    const int fpx = tid >> 2;
    const int fcp = tid & 3;
    // tail: warp 0 covers px 256,257 x 16 cp
    const int tpx = 256 + (lane >> 4);
    const int tcp = lane & 15;

    // ---- prefetch group g into regs (LDG + cvt) ----
    auto prefetch = [&](int g, uint32_t pf[8], uint32_t& pft) {
        const int dy = g >> 2, chunk = g & 3;
        const int yr = y + dy - 1;
        const bool yok = (unsigned)yr < (unsigned)HH;
        const int c0 = chunk * 32;
        const float* xp = x + (((size_t)b * CIN + c0) * HH + yr) * WW;
        #pragma unroll
        for (int jj = 0; jj < 2; jj++) {
            const int px = jj * 128 + fpx;
            const int gx = px - 1;
            const bool ok = yok && ((unsigned)gx < (unsigned)WW);
            #pragma unroll
            for (int ii = 0; ii < 4; ii++) {
                const int cp = fcp + ii * 4;
                float v0 = 0.f, v1 = 0.f;
                if (ok) {
                    v0 = __ldg(xp + (size_t)(2 * cp)     * HH * WW + gx) * styl[c0 + 2 * cp];
                    v1 = __ldg(xp + (size_t)(2 * cp + 1) * HH * WW + gx) * styl[c0 + 2 * cp + 1];
                }
                __half2 hv = __floats2half2_rn(v0, v1);
                pf[jj * 4 + ii] = *(uint32_t*)&hv;
            }
        }
        if (warp == 0) {
            const int gx = tpx - 1;
            float v0 = 0.f, v1 = 0.f;
            if (yok && gx < WW) {
                v0 = __ldg(xp + (size_t)(2 * tcp)     * HH * WW + gx) * styl[c0 + 2 * tcp];
                v1 = __ldg(xp + (size_t)(2 * tcp + 1) * HH * WW + gx) * styl[c0 + 2 * tcp + 1];
            }
            __half2 hv = __floats2half2_rn(v0, v1);
            pft = *(uint32_t*)&hv;
        }
    };

    auto commit = [&](uint32_t* buf, const uint32_t pf[8], uint32_t pft) {
        #pragma unroll
        for (int jj = 0; jj < 2; jj++)
            #pragma unroll
            for (int ii = 0; ii < 4; ii++)
                buf[(jj * 128 + fpx) * PXW + fcp + ii * 4] = pf[jj * 4 + ii];
        if (warp == 0) buf[tpx * PXW + tcp] = pft;
    };

    // ---- one K-step: 32 MMAs/warp; A LDG.128 (L1-hot), B 1 LDS.b32/reg ----
    auto compute = [&](const uint32_t* stg, int dx, int s) {
        #pragma unroll
        for (int kk = 0; kk < 2; kk++) {
            const uint4* As = ((const uint4*)g_wA) +
                              (((size_t)(s * 2 + kk) * 8 + wm * 4) * 32 + lane);
            uint4 af[4];
            #pragma unroll
            for (int m = 0; m < 4; m++) af[m] = __ldg(As + m * 32);

            uint32_t bb[4][2];
            #pragma unroll
            for (int n = 0; n < 4; n++) {
                const int px = wn * 32 + n * 8 + gid + dx;
                const uint32_t* p = stg + px * PXW + kk * 8 + tig;
                bb[n][0] = p[0];
                bb[n][1] = p[4];
            }
            #pragma unroll
            for (int m = 0; m < 4; m++) {
                const uint32_t* a = (const uint32_t*)&af[m];
                #pragma unroll
                for (int n = 0; n < 4; n++)
                    MMA_F16(acc[m][n], a, bb[n]);
            }
        }
    };

    {
        uint32_t pf[8], pft = 0;
        prefetch(0, pf, pft);
        commit(stage[0], pf, pft);
    }
    __syncthreads();

    #pragma unroll 1
    for (int g = 0; g < 12; g++) {
        const int cur = g & 1;
        const int s0  = g * 3;
        uint32_t pf[8], pft = 0;
        if (g < 11) prefetch(g + 1, pf, pft);   // LDG in flight across 3 computes
        compute(stage[cur], 0, s0);
        compute(stage[cur], 1, s0 + 1);
        compute(stage[cur], 2, s0 + 2);
        if (g < 11) commit(stage[cur ^ 1], pf, pft);
        __syncthreads();
    }

    // ---- epilogue: demod + bias, float2 stores ----
    #pragma unroll
    for (int m = 0; m < 4; m++) {
        const int oc0 = (wm * 4 + m) * 16 + gid;
        const int oc1 = oc0 + 8;
        const float d0 = g_demod[b * COUT + oc0], bb0 = bias[oc0];
        const float d1 = g_demod[b * COUT + oc1], bb1 = bias[oc1];
        float* r0 = out + (((size_t)b * COUT + oc0) * HH + y) * WW;
        float* r1 = out + (((size_t)b * COUT + oc1) * HH + y) * WW;
        #pragma unroll
        for (int n = 0; n < 4; n++) {
            const int px = wn * 32 + n * 8 + tig * 2;
            float2 v0 = make_float2(acc[m][n][0] * d0 + bb0, acc[m][n][1] * d0 + bb0);
            float2 v1 = make_float2(acc[m][n][2] * d1 + bb1, acc[m][n][3] * d1 + bb1);
            *(float2*)(r0 + px) = v0;
            *(float2*)(r1 + px) = v1;
        }
    }
}

// ---------------------------------------------------------------------------
extern "C" void kernel_launch(void* const* d_in, const int* in_sizes, int n_in,
                              void* d_out, int out_size) {
    const float* x       = (const float*)d_in[0];
    const float* w       = (const float*)d_in[1];
    const float* weight  = (const float*)d_in[2];
    const float* style_W = (const float*)d_in[3];
    const float* style_b = (const float*)d_in[4];
    const float* bias    = (const float*)d_in[5];
    float* out = (float*)d_out;

    prep1<<<192, 256>>>(w, style_W, style_b, weight);
    prep2<<<1280, 256>>>(weight);

    dim3 grid(HH, Bq);
    conv_mma_kernel<<<grid, 512>>>(x, bias, out);
}